// round 14
// baseline (speedup 1.0000x reference)
#include <cuda_runtime.h>
#include <cstdint>

#define NRMAX   512
#define MAXPER  256
#define TPB     128
#define WPB     4
#define HD      128
#define RD      64
#define WIN     8              // elements per warp-window (16 A-rows: 8 src + 8 dst)
#define RSTRIDE 136            // floats per A row (128 + pad -> conflict-free LDS.64)
#define BUFFL   (16 * RSTRIDE) // floats per A buffer (16 rows)
#define NBF     2048           // B fragments (uint2), 16 KB
#define GRID_C  304

__device__ int g_cursor[NRMAX];
__device__ int g_wcnt[NRMAX];
__device__ int g_order[NRMAX];
__device__ int g_next;
__device__ int g_perm[NRMAX * MAXPER];

// ---------- helpers ----------
__device__ __forceinline__ uint32_t smem_u32(const void* p) {
    uint32_t a;
    asm("{ .reg .u64 t; cvta.to.shared.u64 t, %1; cvt.u32.u64 %0, t; }"
        : "=r"(a) : "l"(p));
    return a;
}
__device__ __forceinline__ void cp_async16(uint32_t s, const void* g) {
    asm volatile("cp.async.cg.shared.global [%0], [%1], 16;" :: "r"(s), "l"(g));
}
#define CP_COMMIT() asm volatile("cp.async.commit_group;" ::: "memory")
#define CP_WAIT(n)  asm volatile("cp.async.wait_group %0;" :: "n"(n) : "memory")

__device__ __forceinline__ uint32_t pack_bf16x2(float hi, float lo) {
    uint32_t r;
    asm("cvt.rn.bf16x2.f32 %0, %1, %2;" : "=r"(r) : "f"(hi), "f"(lo));
    return r;
}
__device__ __forceinline__ void mma_bf16(float c[4], uint32_t a0, uint32_t a1,
                                         uint32_t a2, uint32_t a3,
                                         uint32_t b0, uint32_t b1) {
    asm volatile(
        "mma.sync.aligned.m16n8k16.row.col.f32.bf16.bf16.f32 "
        "{%0,%1,%2,%3}, {%4,%5,%6,%7}, {%8,%9}, {%0,%1,%2,%3};"
        : "+f"(c[0]), "+f"(c[1]), "+f"(c[2]), "+f"(c[3])
        : "r"(a0), "r"(a1), "r"(a2), "r"(a3), "r"(b0), "r"(b1));
}

// ---------- pass 1: fused privatized scatter ----------
__global__ void k_scatter(const int* __restrict__ rel, int n) {
    __shared__ int s_cnt[NRMAX], s_base[NRMAX];
    for (int i = threadIdx.x; i < NRMAX; i += blockDim.x) s_cnt[i] = 0;
    __syncthreads();
    int base = blockIdx.x * blockDim.x * 4;
    int rl[4], lr[4];
    #pragma unroll
    for (int k = 0; k < 4; k++) {
        int i = base + k * blockDim.x + threadIdx.x;
        if (i < n) { rl[k] = rel[i]; lr[k] = atomicAdd(&s_cnt[rl[k]], 1); }
        else rl[k] = -1;
    }
    __syncthreads();
    for (int i = threadIdx.x; i < NRMAX; i += blockDim.x)
        if (s_cnt[i]) s_base[i] = atomicAdd(&g_cursor[i], s_cnt[i]);
    __syncthreads();
    #pragma unroll
    for (int k = 0; k < 4; k++) {
        int i = base + k * blockDim.x + threadIdx.x;
        if (rl[k] >= 0) {
            int p = s_base[rl[k]] + lr[k];
            if (p < MAXPER) g_perm[rl[k] * MAXPER + p] = i;
        }
    }
}

// ---------- pass 2: plan — counts, descending rank, resets ----------
__global__ void k_plan() {
    __shared__ int s_c[NRMAX];
    int t = threadIdx.x;
    int c = g_cursor[t];
    if (c > MAXPER) c = MAXPER;
    g_wcnt[t]   = c;
    g_cursor[t] = 0;
    if (t == 0) g_next = 0;
    s_c[t] = c;
    __syncthreads();
    int rank = 0;
    for (int i = 0; i < NRMAX; i++) {
        int ci = s_c[i];
        rank += (ci > c) || (ci == c && i < t);
    }
    g_order[rank] = t;
}

// ---------- pass 3: compute — bf16 m16n8k16 mma, persistent sorted queue ----
// warp-window of 8 elements -> A[16x128] (rows 0-7 src, 8-15 dst).
// lane: g = lane>>2 (element), t4 = lane&3.
__global__ __launch_bounds__(TPB, 2) void k_compute(
    const int*   __restrict__ src,
    const int*   __restrict__ dst,
    const float* __restrict__ ent,
    const float* __restrict__ relemb,
    const float* __restrict__ proj,
    float*       __restrict__ out)
{
    extern __shared__ float smem[];
    uint2* s_bf  = (uint2*)smem;              // NBF bf16x2-pair B fragments (16 KB)
    float* s_emb = smem + NBF * 2;            // WPB * 2 * BUFFL floats
    __shared__ int s_wi[WPB][2][WIN];
    __shared__ int s_rid;

    int tid  = threadIdx.x;
    int lane = tid & 31;
    int warp = tid >> 5;
    int g    = lane >> 2;
    int t4   = lane & 3;
    unsigned qmask = 0xFu << (lane & 28);     // quad sharing element g

    // staging role: row = lane>>1 (0..15), half = lane&1
    int row_st  = lane >> 1;
    int half_st = lane & 1;
    int e_st    = row_st & 7;
    int sel_st  = row_st >> 3;

    uint32_t emb_u32 = smem_u32(s_emb);
    float* mybuf0 = s_emb + (warp * 2) * BUFFL;

    for (;;) {
        if (tid == 0) s_rid = atomicAdd(&g_next, 1);
        __syncthreads();
        int idx = s_rid;
        if (idx >= NRMAX) break;
        int r_id = g_order[idx];
        int cnt  = g_wcnt[r_id];

        if (cnt > 0) {
            // stage proj into bf16 B-fragment layout, once per relation.
            // entry ii = (kt*8 + nt)*32 + lane2; lane2=(gg,tt):
            //   .x = {hi=P[k0+2tt+1][r], lo=P[k0+2tt][r]},
            //   .y = {hi=P[k0+2tt+9][r], lo=P[k0+2tt+8][r]},  r = nt*8+gg
            {
                const float* P = proj + (size_t)r_id * (HD * RD);
                for (int ii = tid; ii < NBF; ii += TPB) {
                    int lane2 = ii & 31;
                    int ntile = (ii >> 5) & 7;
                    int ktile = ii >> 8;
                    int gg = lane2 >> 2, tt = lane2 & 3;
                    int r  = ntile * 8 + gg;
                    int k0 = ktile * 16 + 2 * tt;
                    float p0 = __ldg(P + (size_t)(k0    ) * RD + r);
                    float p1 = __ldg(P + (size_t)(k0 + 1) * RD + r);
                    float p2 = __ldg(P + (size_t)(k0 + 8) * RD + r);
                    float p3 = __ldg(P + (size_t)(k0 + 9) * RD + r);
                    s_bf[ii] = make_uint2(pack_bf16x2(p1, p0),
                                          pack_bf16x2(p3, p2));
                }
            }
            __syncthreads();

            // rel_emb per lane: cols nt*8 + 2*t4 (+1)
            const float2* rr2 = (const float2*)(relemb + (size_t)r_id * RD);
            float2 rv[8];
            #pragma unroll
            for (int nt = 0; nt < 8; nt++) rv[nt] = rr2[nt * 4 + t4];

            const int* bucket = g_perm + r_id * MAXPER;
            int nwin = (cnt + WIN - 1) >> 3;

            auto stage = [&](int w, int b) {
                int pos  = w * WIN + e_st;
                bool ok  = pos < cnt;
                int pidx = bucket[ok ? pos : (cnt - 1)];
                if (sel_st == 0 && half_st == 0)
                    s_wi[warp][b][e_st] = ok ? pidx : -1;
                int node = sel_st ? dst[pidx] : src[pidx];
                const float4* erow = (const float4*)(ent + (size_t)node * HD);
                uint32_t d32 = emb_u32 +
                    (((warp * 2 + b) * BUFFL + row_st * RSTRIDE + half_st * 64) << 2);
                #pragma unroll
                for (int q = 0; q < 16; q++)
                    cp_async16(d32 + q * 16, erow + half_st * 16 + q);
                CP_COMMIT();
            };

            int b = 0;
            if (warp < nwin) stage(warp, 0);

            for (int w = warp; w < nwin; w += WPB) {
                int wn = w + WPB;
                if (wn < nwin) { stage(wn, b ^ 1); CP_WAIT(1); }
                else           { CP_WAIT(0); }
                __syncwarp();

                const float* A = mybuf0 + b * BUFFL;
                float c[8][4];
                #pragma unroll
                for (int nt = 0; nt < 8; nt++)
                    #pragma unroll
                    for (int p = 0; p < 4; p++) c[nt][p] = 0.f;

                #pragma unroll
                for (int kt = 0; kt < 8; kt++) {
                    int k0 = kt * 16 + 2 * t4;
                    const float* Ag  = A + g * RSTRIDE + k0;
                    const float* Ag8 = A + (g + 8) * RSTRIDE + k0;
                    float2 s0 = *(const float2*)(Ag);
                    float2 s1 = *(const float2*)(Ag8);
                    float2 s2 = *(const float2*)(Ag + 8);
                    float2 s3 = *(const float2*)(Ag8 + 8);
                    uint32_t a0 = pack_bf16x2(s0.y, s0.x);
                    uint32_t a1 = pack_bf16x2(s1.y, s1.x);
                    uint32_t a2 = pack_bf16x2(s2.y, s2.x);
                    uint32_t a3 = pack_bf16x2(s3.y, s3.x);
                    const uint2* B2 = s_bf + kt * 256 + lane;
                    #pragma unroll
                    for (int nt = 0; nt < 8; nt++) {
                        uint2 bb = B2[nt * 32];
                        mma_bf16(c[nt], a0, a1, a2, a3, bb.x, bb.y);
                    }
                }

                // epilogue: lane holds src elem g at (c[nt][0],c[nt][1]),
                // dst elem g at (c[nt][2],c[nt][3]), cols nt*8 + 2*t4 (+1)
                float ss = 0.f, dd = 0.f;
                #pragma unroll
                for (int nt = 0; nt < 8; nt++) {
                    ss += c[nt][0]*c[nt][0] + c[nt][1]*c[nt][1];
                    dd += c[nt][2]*c[nt][2] + c[nt][3]*c[nt][3];
                }
                #pragma unroll
                for (int o = 2; o > 0; o >>= 1) {
                    ss += __shfl_xor_sync(qmask, ss, o);
                    dd += __shfl_xor_sync(qmask, dd, o);
                }
                float inv_s = 1.f / fmaxf(sqrtf(ss), 1e-12f);
                float inv_d = 1.f / fmaxf(sqrtf(dd), 1e-12f);

                float sc = 0.f;
                #pragma unroll
                for (int nt = 0; nt < 8; nt++) {
                    float d0 = c[nt][0] * inv_s + rv[nt].x - c[nt][2] * inv_d;
                    float d1 = c[nt][1] * inv_s + rv[nt].y - c[nt][3] * inv_d;
                    sc += d0 * d0 + d1 * d1;
                }
                #pragma unroll
                for (int o = 2; o > 0; o >>= 1)
                    sc += __shfl_xor_sync(qmask, sc, o);

                if (t4 == 0) {
                    int oi = s_wi[warp][b][g];
                    if (oi >= 0) out[oi] = sqrtf(sc);
                }
                b ^= 1;
            }
        }
        __syncthreads();
    }
}

// ---------- launch ----------
extern "C" void kernel_launch(void* const* d_in, const int* in_sizes, int n_in,
                              void* d_out, int out_size) {
    const int*   src = (const int*)d_in[0];
    const int*   rel = (const int*)d_in[1];
    const int*   dst = (const int*)d_in[2];
    const float* ent = (const float*)d_in[3];
    const float* rle = (const float*)d_in[4];
    const float* prj = (const float*)d_in[5];
    float*       out = (float*)d_out;

    int B = in_sizes[0];

    const int SMEM_BYTES = NBF * 8 + WPB * 2 * BUFFL * 4;  // 16384+69632=86016
    cudaFuncSetAttribute(k_compute, cudaFuncAttributeMaxDynamicSharedMemorySize,
                         SMEM_BYTES);

    int gS = (B + 256 * 4 - 1) / (256 * 4);   // 64 blocks

    k_scatter<<<gS, 256>>>(rel, B);
    k_plan<<<1, NRMAX>>>();
    k_compute<<<GRID_C, TPB, SMEM_BYTES>>>(src, dst, ent, rle, prj, out);
}

// round 16
// speedup vs baseline: 1.4029x; 1.4029x over previous
#include <cuda_runtime.h>
#include <cstdint>

#define NRMAX   512
#define MAXPER  256
#define TPB     128
#define WPB     4
#define HD      128
#define RD      64
#define WIN     8              // elements per warp-window (16 A-rows: 8 src + 8 dst)
#define RSTRIDE 136            // floats per A row (128 + pad)
#define BUFFL   (16 * RSTRIDE) // floats per A buffer (16 rows)
#define NBF     2048           // B fragments (uint2), 16 KB
#define PSTRIDE 68             // padded proj scratch row (floats)

__device__ int g_cursor[NRMAX];
__device__ int g_perm[NRMAX * MAXPER];

// ---------- helpers ----------
__device__ __forceinline__ uint32_t smem_u32(const void* p) {
    uint32_t a;
    asm("{ .reg .u64 t; cvta.to.shared.u64 t, %1; cvt.u32.u64 %0, t; }"
        : "=r"(a) : "l"(p));
    return a;
}
__device__ __forceinline__ void cp_async16(uint32_t s, const void* g) {
    asm volatile("cp.async.cg.shared.global [%0], [%1], 16;" :: "r"(s), "l"(g));
}
#define CP_COMMIT() asm volatile("cp.async.commit_group;" ::: "memory")
#define CP_WAIT(n)  asm volatile("cp.async.wait_group %0;" :: "n"(n) : "memory")

__device__ __forceinline__ uint32_t pack_bf16x2(float hi, float lo) {
    uint32_t r;
    asm("cvt.rn.bf16x2.f32 %0, %1, %2;" : "=r"(r) : "f"(hi), "f"(lo));
    return r;
}
__device__ __forceinline__ void mma_bf16(float c[4], uint32_t a0, uint32_t a1,
                                         uint32_t a2, uint32_t a3,
                                         uint32_t b0, uint32_t b1) {
    asm volatile(
        "mma.sync.aligned.m16n8k16.row.col.f32.bf16.bf16.f32 "
        "{%0,%1,%2,%3}, {%4,%5,%6,%7}, {%8,%9}, {%0,%1,%2,%3};"
        : "+f"(c[0]), "+f"(c[1]), "+f"(c[2]), "+f"(c[3])
        : "r"(a0), "r"(a1), "r"(a2), "r"(a3), "r"(b0), "r"(b1));
}

// ---------- pass 1: fused privatized scatter ----------
__global__ void k_scatter(const int* __restrict__ rel, int n) {
    __shared__ int s_cnt[NRMAX], s_base[NRMAX];
    for (int i = threadIdx.x; i < NRMAX; i += blockDim.x) s_cnt[i] = 0;
    __syncthreads();
    int base = blockIdx.x * blockDim.x * 4;
    int rl[4], lr[4];
    #pragma unroll
    for (int k = 0; k < 4; k++) {
        int i = base + k * blockDim.x + threadIdx.x;
        if (i < n) { rl[k] = rel[i]; lr[k] = atomicAdd(&s_cnt[rl[k]], 1); }
        else rl[k] = -1;
    }
    __syncthreads();
    for (int i = threadIdx.x; i < NRMAX; i += blockDim.x)
        if (s_cnt[i]) s_base[i] = atomicAdd(&g_cursor[i], s_cnt[i]);
    __syncthreads();
    #pragma unroll
    for (int k = 0; k < 4; k++) {
        int i = base + k * blockDim.x + threadIdx.x;
        if (rl[k] >= 0) {
            int p = s_base[rl[k]] + lr[k];
            if (p < MAXPER) g_perm[rl[k] * MAXPER + p] = i;
        }
    }
}

// ---------- pass 2: compute — bf16 m16n8k16, block per relation ----------
// warp-window of 8 elements -> A[16x128] (rows 0-7 src, 8-15 dst).
// consumer lane: g = lane>>2 (element), t4 = lane&3.
__global__ __launch_bounds__(TPB) void k_compute(
    const int*   __restrict__ src,
    const int*   __restrict__ dst,
    const float* __restrict__ ent,
    const float* __restrict__ relemb,
    const float* __restrict__ proj,
    float*       __restrict__ out)
{
    extern __shared__ char smemc[];
    uint2* s_bf  = (uint2*)smemc;             // NBF B fragments (16 KB)
    float* s_emb = (float*)(smemc + NBF * 8); // A buffers / proj scratch overlay
    __shared__ int s_wi[WPB][2][WIN];

    int r_id = blockIdx.x;
    int cnt  = g_cursor[r_id];
    if (cnt > MAXPER) cnt = MAXPER;
    __syncthreads();
    if (threadIdx.x == 0) g_cursor[r_id] = 0;  // reset for next replay
    if (cnt == 0) return;

    int tid  = threadIdx.x;
    int lane = tid & 31;
    int warp = tid >> 5;
    int g    = lane >> 2;
    int t4   = lane & 3;
    unsigned qmask = 0xFu << (lane & 28);

    // staging role: row = lane>>1 (0..15), half = lane&1
    int row_st  = lane >> 1;
    int half_st = lane & 1;
    int e_st    = row_st & 7;
    int sel_st  = row_st >> 3;

    // ---- phase a: coalesced copy proj -> padded SMEM scratch [128][68] ----
    {
        float* P_s = s_emb;
        const float4* p4 = (const float4*)(proj + (size_t)r_id * (HD * RD));
        for (int i = tid; i < HD * RD / 4; i += TPB) {
            int k = i >> 4, c = i & 15;
            *(float4*)(P_s + k * PSTRIDE + c * 4) = p4[i];
        }
    }
    __syncthreads();

    // ---- phase b: build B fragments from SMEM (conflict-free LDS.64) ----
    // task t = (kt,tt); lane rp covers r = {2rp, 2rp+1}
    {
        const float* P_s = s_emb;
        for (int t = warp; t < 32; t += WPB) {
            int kt = t >> 2, tt = t & 3;
            int k0 = kt * 16 + 2 * tt;
            int rp = lane;
            float2 L0 = *(const float2*)(P_s + (k0    ) * PSTRIDE + 2 * rp);
            float2 L1 = *(const float2*)(P_s + (k0 + 1) * PSTRIDE + 2 * rp);
            float2 L8 = *(const float2*)(P_s + (k0 + 8) * PSTRIDE + 2 * rp);
            float2 L9 = *(const float2*)(P_s + (k0 + 9) * PSTRIDE + 2 * rp);
            int nt = rp >> 2, gg = 2 * (rp & 3);
            int ii = (kt * 8 + nt) * 32 + gg * 4 + tt;
            s_bf[ii]     = make_uint2(pack_bf16x2(L1.x, L0.x),
                                      pack_bf16x2(L9.x, L8.x));
            s_bf[ii + 4] = make_uint2(pack_bf16x2(L1.y, L0.y),
                                      pack_bf16x2(L9.y, L8.y));
        }
    }

    // rel_emb per lane: cols nt*8 + 2*t4 (+1)
    const float2* rr2 = (const float2*)(relemb + (size_t)r_id * RD);
    float2 rv[8];
    #pragma unroll
    for (int nt = 0; nt < 8; nt++) rv[nt] = rr2[nt * 4 + t4];

    __syncthreads();   // fragments done; A buffers may now overwrite scratch

    uint32_t emb_u32 = smem_u32(s_emb);
    float* mybuf0 = s_emb + (warp * 2) * BUFFL;
    const int* bucket = g_perm + r_id * MAXPER;
    int nwin = (cnt + WIN - 1) >> 3;

    auto stage = [&](int w, int b) {
        int pos  = w * WIN + e_st;
        bool ok  = pos < cnt;
        int pidx = bucket[ok ? pos : (cnt - 1)];
        if (sel_st == 0 && half_st == 0)
            s_wi[warp][b][e_st] = ok ? pidx : -1;
        int node = sel_st ? dst[pidx] : src[pidx];
        const float4* erow = (const float4*)(ent + (size_t)node * HD);
        uint32_t d32 = emb_u32 +
            (((warp * 2 + b) * BUFFL + row_st * RSTRIDE + half_st * 64) << 2);
        #pragma unroll
        for (int q = 0; q < 16; q++)
            cp_async16(d32 + q * 16, erow + half_st * 16 + q);
        CP_COMMIT();
    };

    int b = 0;
    if (warp < nwin) stage(warp, 0);

    for (int w = warp; w < nwin; w += WPB) {
        int wn = w + WPB;
        if (wn < nwin) { stage(wn, b ^ 1); CP_WAIT(1); }
        else           { CP_WAIT(0); }
        __syncwarp();

        const float* A = mybuf0 + b * BUFFL;
        float c[8][4];
        #pragma unroll
        for (int nt = 0; nt < 8; nt++)
            #pragma unroll
            for (int p = 0; p < 4; p++) c[nt][p] = 0.f;

        #pragma unroll
        for (int kt = 0; kt < 8; kt++) {
            int k0 = kt * 16 + 2 * t4;
            const float* Ag  = A + g * RSTRIDE + k0;
            const float* Ag8 = A + (g + 8) * RSTRIDE + k0;
            float2 s0 = *(const float2*)(Ag);
            float2 s1 = *(const float2*)(Ag8);
            float2 s2 = *(const float2*)(Ag + 8);
            float2 s3 = *(const float2*)(Ag8 + 8);
            uint32_t a0 = pack_bf16x2(s0.y, s0.x);
            uint32_t a1 = pack_bf16x2(s1.y, s1.x);
            uint32_t a2 = pack_bf16x2(s2.y, s2.x);
            uint32_t a3 = pack_bf16x2(s3.y, s3.x);
            const uint2* B2 = s_bf + kt * 256 + lane;
            #pragma unroll
            for (int nt = 0; nt < 8; nt++) {
                uint2 bb = B2[nt * 32];
                mma_bf16(c[nt], a0, a1, a2, a3, bb.x, bb.y);
            }
        }

        // epilogue: lane holds src elem g at (c[nt][0],c[nt][1]),
        // dst elem g at (c[nt][2],c[nt][3]), cols nt*8 + 2*t4 (+1)
        float ss = 0.f, dd = 0.f;
        #pragma unroll
        for (int nt = 0; nt < 8; nt++) {
            ss += c[nt][0]*c[nt][0] + c[nt][1]*c[nt][1];
            dd += c[nt][2]*c[nt][2] + c[nt][3]*c[nt][3];
        }
        #pragma unroll
        for (int o = 2; o > 0; o >>= 1) {
            ss += __shfl_xor_sync(qmask, ss, o);
            dd += __shfl_xor_sync(qmask, dd, o);
        }
        float inv_s = 1.f / fmaxf(sqrtf(ss), 1e-12f);
        float inv_d = 1.f / fmaxf(sqrtf(dd), 1e-12f);

        float sc = 0.f;
        #pragma unroll
        for (int nt = 0; nt < 8; nt++) {
            float d0 = c[nt][0] * inv_s + rv[nt].x - c[nt][2] * inv_d;
            float d1 = c[nt][1] * inv_s + rv[nt].y - c[nt][3] * inv_d;
            sc += d0 * d0 + d1 * d1;
        }
        #pragma unroll
        for (int o = 2; o > 0; o >>= 1)
            sc += __shfl_xor_sync(qmask, sc, o);

        if (t4 == 0) {
            int oi = s_wi[warp][b][g];
            if (oi >= 0) out[oi] = sqrtf(sc);
        }
        b ^= 1;
    }
}

// ---------- launch ----------
extern "C" void kernel_launch(void* const* d_in, const int* in_sizes, int n_in,
                              void* d_out, int out_size) {
    const int*   src = (const int*)d_in[0];
    const int*   rel = (const int*)d_in[1];
    const int*   dst = (const int*)d_in[2];
    const float* ent = (const float*)d_in[3];
    const float* rle = (const float*)d_in[4];
    const float* prj = (const float*)d_in[5];
    float*       out = (float*)d_out;

    int B  = in_sizes[0];
    int NR = in_sizes[4] / RD;

    const int SMEM_BYTES = NBF * 8 + WPB * 2 * BUFFL * 4;  // 16384+69632=86016
    cudaFuncSetAttribute(k_compute, cudaFuncAttributeMaxDynamicSharedMemorySize,
                         SMEM_BYTES);

    int gS = (B + 256 * 4 - 1) / (256 * 4);   // 64 blocks

    k_scatter<<<gS, 256>>>(rel, B);
    k_compute<<<NR, TPB, SMEM_BYTES>>>(src, dst, ent, rle, prj, out);
}

// round 17
// speedup vs baseline: 1.5015x; 1.0703x over previous
#include <cuda_runtime.h>
#include <cstdint>

#define NRMAX   512
#define MAXPER  256
#define TPB     256
#define WPB     8
#define HD      128
#define RD      64
#define WIN     8              // elements per warp-window (16 A-rows: 8 src + 8 dst)
#define NBF     2048           // B fragments (uint2), 16 KB
#define PSTRIDE 68             // padded proj scratch row (floats)
#define UI4G    33             // uint4 per g-row in A-frag buffer (32 + 1 pad)
#define BUF4    (8 * UI4G)     // uint4 per A buffer (8 g-rows) = 4224 B

__device__ int g_cursor[NRMAX];
__device__ int g_perm[NRMAX * MAXPER];

// ---------- helpers ----------
__device__ __forceinline__ uint32_t pack_bf16x2(float hi, float lo) {
    uint32_t r;
    asm("cvt.rn.bf16x2.f32 %0, %1, %2;" : "=r"(r) : "f"(hi), "f"(lo));
    return r;
}
__device__ __forceinline__ void mma_bf16(float c[4], uint32_t a0, uint32_t a1,
                                         uint32_t a2, uint32_t a3,
                                         uint32_t b0, uint32_t b1) {
    asm volatile(
        "mma.sync.aligned.m16n8k16.row.col.f32.bf16.bf16.f32 "
        "{%0,%1,%2,%3}, {%4,%5,%6,%7}, {%8,%9}, {%0,%1,%2,%3};"
        : "+f"(c[0]), "+f"(c[1]), "+f"(c[2]), "+f"(c[3])
        : "r"(a0), "r"(a1), "r"(a2), "r"(a3), "r"(b0), "r"(b1));
}

// ---------- pass 1: fused privatized scatter ----------
__global__ void k_scatter(const int* __restrict__ rel, int n) {
    __shared__ int s_cnt[NRMAX], s_base[NRMAX];
    for (int i = threadIdx.x; i < NRMAX; i += blockDim.x) s_cnt[i] = 0;
    __syncthreads();
    int base = blockIdx.x * blockDim.x * 4;
    int rl[4], lr[4];
    #pragma unroll
    for (int k = 0; k < 4; k++) {
        int i = base + k * blockDim.x + threadIdx.x;
        if (i < n) { rl[k] = rel[i]; lr[k] = atomicAdd(&s_cnt[rl[k]], 1); }
        else rl[k] = -1;
    }
    __syncthreads();
    for (int i = threadIdx.x; i < NRMAX; i += blockDim.x)
        if (s_cnt[i]) s_base[i] = atomicAdd(&g_cursor[i], s_cnt[i]);
    __syncthreads();
    #pragma unroll
    for (int k = 0; k < 4; k++) {
        int i = base + k * blockDim.x + threadIdx.x;
        if (rl[k] >= 0) {
            int p = s_base[rl[k]] + lr[k];
            if (p < MAXPER) g_perm[rl[k] * MAXPER + p] = i;
        }
    }
}

// ---------- pass 2: compute — bf16 m16n8k16, block per relation, 8 warps ----
// warp-window of 8 elements; A staged as ready-made bf16 fragments:
// uint4 at (g,kt,t4): {a0=src[g] k0:k0+1, a1=dst[g], a2=src[g] +8, a3=dst[g] +8}
__global__ __launch_bounds__(TPB, 2) void k_compute(
    const int*   __restrict__ src,
    const int*   __restrict__ dst,
    const float* __restrict__ ent,
    const float* __restrict__ relemb,
    const float* __restrict__ proj,
    float*       __restrict__ out)
{
    extern __shared__ char smemc[];
    uint2* s_bf = (uint2*)smemc;              // NBF B fragments (16 KB)
    uint4* s_A  = (uint4*)(smemc + NBF * 8);  // A-frag buffers / proj scratch
    __shared__ int s_wi[WPB][2][WIN];

    int r_id = blockIdx.x;
    int cnt  = g_cursor[r_id];
    if (cnt > MAXPER) cnt = MAXPER;
    __syncthreads();
    if (threadIdx.x == 0) g_cursor[r_id] = 0;  // reset for next replay
    if (cnt == 0) return;

    int tid  = threadIdx.x;
    int lane = tid & 31;
    int warp = tid >> 5;
    int g    = lane >> 2;
    int t4   = lane & 3;
    unsigned qmask = 0xFu << (lane & 28);

    // staging role: row = lane>>1 (0..15), half = lane&1
    int row_st  = lane >> 1;
    int half_st = lane & 1;
    int e_st    = row_st & 7;
    int sel_st  = row_st >> 3;

    // ---- phase a: coalesced copy proj -> padded SMEM scratch [128][68] ----
    {
        float* P_s = (float*)s_A;
        const float4* p4 = (const float4*)(proj + (size_t)r_id * (HD * RD));
        for (int i = tid; i < HD * RD / 4; i += TPB) {
            int k = i >> 4, c = i & 15;
            *(float4*)(P_s + k * PSTRIDE + c * 4) = p4[i];
        }
    }
    __syncthreads();

    // ---- phase b: build B fragments from scratch (conflict-free LDS.64) ----
    {
        const float* P_s = (const float*)s_A;
        for (int t = warp; t < 32; t += WPB) {
            int kt = t >> 2, tt = t & 3;
            int k0 = kt * 16 + 2 * tt;
            int rp = lane;
            float2 L0 = *(const float2*)(P_s + (k0    ) * PSTRIDE + 2 * rp);
            float2 L1 = *(const float2*)(P_s + (k0 + 1) * PSTRIDE + 2 * rp);
            float2 L8 = *(const float2*)(P_s + (k0 + 8) * PSTRIDE + 2 * rp);
            float2 L9 = *(const float2*)(P_s + (k0 + 9) * PSTRIDE + 2 * rp);
            int nt = rp >> 2, gg = 2 * (rp & 3);
            int ii = (kt * 8 + nt) * 32 + gg * 4 + tt;
            s_bf[ii]     = make_uint2(pack_bf16x2(L1.x, L0.x),
                                      pack_bf16x2(L9.x, L8.x));
            s_bf[ii + 4] = make_uint2(pack_bf16x2(L1.y, L0.y),
                                      pack_bf16x2(L9.y, L8.y));
        }
    }

    // rel_emb per lane: cols nt*8 + 2*t4 (+1)
    const float2* rr2 = (const float2*)(relemb + (size_t)r_id * RD);
    float2 rv[8];
    #pragma unroll
    for (int nt = 0; nt < 8; nt++) rv[nt] = rr2[nt * 4 + t4];

    __syncthreads();   // fragments done; A buffers may now overwrite scratch

    uint4* mybuf = s_A + warp * 2 * BUF4;
    const int* bucket = g_perm + r_id * MAXPER;
    int nwin = (cnt + WIN - 1) >> 3;

    // stage window w into buffer b: LDG -> cvt -> STS (bf16 fragments)
    auto stage = [&](int w, int b) {
        int pos  = w * WIN + e_st;
        bool ok  = pos < cnt;
        int pidx = bucket[ok ? pos : (cnt - 1)];
        if (sel_st == 0 && half_st == 0)
            s_wi[warp][b][e_st] = ok ? pidx : -1;
        int node = sel_st ? dst[pidx] : src[pidx];
        const float4* erow = (const float4*)(ent + (size_t)node * HD) + half_st * 16;
        float4 f[16];
        #pragma unroll
        for (int q = 0; q < 16; q++) f[q] = erow[q];
        const float* fa = (const float*)f;
        uint32_t* bu = (uint32_t*)(mybuf + b * BUF4);
        #pragma unroll
        for (int kj = 0; kj < 4; kj++) {
            #pragma unroll
            for (int t = 0; t < 4; t++) {
                int L  = 16 * kj + 2 * t;
                int i4 = e_st * UI4G + (4 * half_st + kj) * 4 + t;
                bu[i4 * 4 + sel_st]     = pack_bf16x2(fa[L + 1], fa[L]);
                bu[i4 * 4 + sel_st + 2] = pack_bf16x2(fa[L + 9], fa[L + 8]);
            }
        }
    };

    int b = 0;
    if (warp < nwin) stage(warp, 0);

    for (int w = warp; w < nwin; w += WPB) {
        int wn = w + WPB;
        __syncwarp();                 // prev compute reads done before overwrite
        if (wn < nwin) stage(wn, b ^ 1);
        __syncwarp();                 // current buffer's STS visible

        const uint4* Af = mybuf + b * BUF4;
        float c[8][4];
        #pragma unroll
        for (int nt = 0; nt < 8; nt++)
            #pragma unroll
            for (int p = 0; p < 4; p++) c[nt][p] = 0.f;

        #pragma unroll
        for (int kt = 0; kt < 8; kt++) {
            uint4 q = Af[g * UI4G + kt * 4 + t4];
            const uint2* B2 = s_bf + kt * 256 + lane;
            #pragma unroll
            for (int nt = 0; nt < 8; nt++) {
                uint2 bb = B2[nt * 32];
                mma_bf16(c[nt], q.x, q.y, q.z, q.w, bb.x, bb.y);
            }
        }

        // epilogue: lane holds src elem g at (c[nt][0],c[nt][1]),
        // dst elem g at (c[nt][2],c[nt][3]), cols nt*8 + 2*t4 (+1)
        float ss = 0.f, dd = 0.f;
        #pragma unroll
        for (int nt = 0; nt < 8; nt++) {
            ss += c[nt][0]*c[nt][0] + c[nt][1]*c[nt][1];
            dd += c[nt][2]*c[nt][2] + c[nt][3]*c[nt][3];
        }
        #pragma unroll
        for (int o = 2; o > 0; o >>= 1) {
            ss += __shfl_xor_sync(qmask, ss, o);
            dd += __shfl_xor_sync(qmask, dd, o);
        }
        float inv_s = 1.f / fmaxf(sqrtf(ss), 1e-12f);
        float inv_d = 1.f / fmaxf(sqrtf(dd), 1e-12f);

        float sc = 0.f;
        #pragma unroll
        for (int nt = 0; nt < 8; nt++) {
            float d0 = c[nt][0] * inv_s + rv[nt].x - c[nt][2] * inv_d;
            float d1 = c[nt][1] * inv_s + rv[nt].y - c[nt][3] * inv_d;
            sc += d0 * d0 + d1 * d1;
        }
        #pragma unroll
        for (int o = 2; o > 0; o >>= 1)
            sc += __shfl_xor_sync(qmask, sc, o);

        if (t4 == 0) {
            int oi = s_wi[warp][b][g];
            if (oi >= 0) out[oi] = sqrtf(sc);
        }
        b ^= 1;
    }
}

// ---------- launch ----------
extern "C" void kernel_launch(void* const* d_in, const int* in_sizes, int n_in,
                              void* d_out, int out_size) {
    const int*   src = (const int*)d_in[0];
    const int*   rel = (const int*)d_in[1];
    const int*   dst = (const int*)d_in[2];
    const float* ent = (const float*)d_in[3];
    const float* rle = (const float*)d_in[4];
    const float* prj = (const float*)d_in[5];
    float*       out = (float*)d_out;

    int B  = in_sizes[0];
    int NR = in_sizes[4] / RD;

    const int SMEM_BYTES = NBF * 8 + WPB * 2 * BUF4 * 16;  // 16384+67584=83968
    cudaFuncSetAttribute(k_compute, cudaFuncAttributeMaxDynamicSharedMemorySize,
                         SMEM_BYTES);

    int gS = (B + 256 * 4 - 1) / (256 * 4);   // 64 blocks

    k_scatter<<<gS, 256>>>(rel, B);
    k_compute<<<NR, TPB, SMEM_BYTES>>>(src, dst, ent, rle, prj, out);
}